// round 8
// baseline (speedup 1.0000x reference)
#include <cuda_runtime.h>

// x: (16, 2, 1024, 1024) fp32, 20 diffusion steps, depthwise 5-point stencil,
// reflect padding. Temporal blocking: K=5 fused steps/pass, 4 passes.
// Round 8: prefetch depth 3, interior/edge specialized loops (SEL-free
// interior), 4-warp blocks for better SM packing (576 blocks).
#define HH 1024
#define WW 1024
#define NPLANES 32
#define PLANE_ELEMS (HH * WW)
#define K 5            // fused timesteps per pass
#define RB 128         // output rows per warp
#define NSTRIP 9       // strip j input base = 112*j, window 128 cols

__device__ float g_scratch[NPLANES * PLANE_ELEMS];

__device__ __forceinline__ int reflect_row(int i) {
    i = (i < 0) ? -i : i;
    return (i >= HH) ? (2 * HH - 2 - i) : i;
}

template<bool EDGEL, bool EDGER>
__device__ __forceinline__ void run_band(
    const float* __restrict__ sp, float* __restrict__ dp,
    int g, int r0, int lane,
    float wu, float wl, float wc, float wr, float wd)
{
    const int lo = EDGEL ? 0 : 2;
    const int hi = EDGER ? 31 : 29;
    const bool do_store = (lane >= lo && lane <= hi);
    const bool fixL = EDGEL && (lane == 0);
    const bool fixR = EDGER && (lane == 31);

    float4 a[K], b[K];
#pragma unroll
    for (int s = 0; s < K; ++s) {
        a[s] = make_float4(0.f, 0.f, 0.f, 0.f);
        b[s] = make_float4(0.f, 0.f, 0.f, 0.f);
    }

    const int niter = RB + 2 * K;   // 138

    // Prefetch pipeline, depth 3 (reflect keeps all rows in-bounds).
    float4 p0 = ((const float4*)(sp + (size_t)reflect_row(r0 - K)     * WW))[g];
    float4 p1 = ((const float4*)(sp + (size_t)reflect_row(r0 - K + 1) * WW))[g];
    float4 p2 = ((const float4*)(sp + (size_t)reflect_row(r0 - K + 2) * WW))[g];

#pragma unroll 2
    for (int m = 0; m < niter; ++m) {
        const int i = r0 - K + m;   // input row index for stage 0

        float4 cur[K + 1];
        cur[0] = p0;
        p0 = p1;
        p1 = p2;
        p2 = ((const float4*)(sp + (size_t)reflect_row(i + 3) * WW))[g];

        // Shuffle batch: operands are iteration-start state only.
        float lv[K], rv[K];
#pragma unroll
        for (int s = 0; s < K; ++s) {
            const float lu = __shfl_up_sync(0xffffffffu, b[s].w, 1);
            const float rd = __shfl_down_sync(0xffffffffu, b[s].x, 1);
            // Interior strips: fixL/fixR are compile-time false -> no SELs.
            lv[s] = (EDGEL && fixL) ? b[s].y : lu;
            rv[s] = (EDGER && fixR) ? b[s].z : rd;
        }

#pragma unroll
        for (int s = 1; s <= K; ++s) {
            const float4 B = b[s - 1];
            const float4 A = a[s - 1];
            const float4 D = cur[s - 1];   // fresh value — consume last

            float4 bs;
            bs.x = fmaf(wu, A.x, fmaf(wl, lv[s - 1], fmaf(wr, B.y, wc * B.x)));
            bs.y = fmaf(wu, A.y, fmaf(wl, B.x,       fmaf(wr, B.z, wc * B.y)));
            bs.z = fmaf(wu, A.z, fmaf(wl, B.y,       fmaf(wr, B.w, wc * B.z)));
            bs.w = fmaf(wu, A.w, fmaf(wl, B.z,       fmaf(wr, rv[s - 1], wc * B.w)));

            float4 o;
            o.x = fmaf(wd, D.x, bs.x);
            o.y = fmaf(wd, D.y, bs.y);
            o.z = fmaf(wd, D.z, bs.z);
            o.w = fmaf(wd, D.w, bs.w);
            cur[s] = o;
        }

        if (m >= 2 * K && do_store) {
            ((float4*)(dp + (size_t)(i - K) * WW))[g] = cur[K];
        }

#pragma unroll
        for (int s = 0; s < K; ++s) {
            a[s] = b[s];
            b[s] = cur[s];
        }
    }
}

__global__ __launch_bounds__(128, 5)
void fused_stencil(const float* __restrict__ src,
                   float* __restrict__ dst,
                   const float* __restrict__ wgt)
{
    const int strip = blockIdx.x;                    // 0..8
    const int img   = blockIdx.y;                    // 0..31
    const int band  = blockIdx.z * 4 + (threadIdx.x >> 5);  // 0..7
    const int lane  = threadIdx.x & 31;

    const float* wp = wgt + (img & 1) * 9;   // OIHW (2,1,3,3), depthwise
    const float wu = wp[1];
    const float wl = wp[3];
    const float wc = wp[4];
    const float wr = wp[5];
    const float wd = wp[7];

    const float* sp = src + (size_t)img * PLANE_ELEMS;
    float*       dp = dst + (size_t)img * PLANE_ELEMS;

    const int g  = ((strip * 112) >> 2) + lane;   // lane's float4 column index
    const int r0 = band * RB;

    if (strip == 0) {
        run_band<true, false>(sp, dp, g, r0, lane, wu, wl, wc, wr, wd);
    } else if (strip == NSTRIP - 1) {
        run_band<false, true>(sp, dp, g, r0, lane, wu, wl, wc, wr, wd);
    } else {
        run_band<false, false>(sp, dp, g, r0, lane, wu, wl, wc, wr, wd);
    }
}

extern "C" void kernel_launch(void* const* d_in, const int* in_sizes, int n_in,
                              void* d_out, int out_size)
{
    const float* x   = (const float*)d_in[0];
    const float* wgt = (const float*)d_in[1];
    float* out = (float*)d_out;

    float* scratch = nullptr;
    cudaGetSymbolAddress((void**)&scratch, g_scratch);

    dim3 grid(NSTRIP, NPLANES, 2);   // 9 strips x 32 planes x 2 = 576 blocks
    dim3 block(128);                 // 4 warps = 4 row bands each

    // 4 passes of 5 fused steps: x -> scratch -> out -> scratch -> out
    fused_stencil<<<grid, block>>>(x,       scratch, wgt);
    fused_stencil<<<grid, block>>>(scratch, out,     wgt);
    fused_stencil<<<grid, block>>>(out,     scratch, wgt);
    fused_stencil<<<grid, block>>>(scratch, out,     wgt);
}

// round 9
// speedup vs baseline: 1.0335x; 1.0335x over previous
#include <cuda_runtime.h>

// x: (16, 2, 1024, 1024) fp32, 20 diffusion steps, depthwise 5-point stencil,
// reflect padding. Round 9: temporal blocking K=7+7+6 in THREE passes
// (vs 4x5) -> 23% fewer row-iterations and ~25% less DRAM traffic.
// Structure = R7 (8-warp blocks, warp-independent strips, shuffle batch,
// dd-last trees, depth-2 prefetch) + R8's compile-time edge specialization.
#define HH 1024
#define WW 1024
#define NPLANES 32
#define PLANE_ELEMS (HH * WW)
#define RB 128         // output rows per warp
#define NSTRIP 9       // strip j input base = 112*j, window 128 cols

__device__ float g_scratch[NPLANES * PLANE_ELEMS];

__device__ __forceinline__ int reflect_row(int i) {
    i = (i < 0) ? -i : i;
    return (i >= HH) ? (2 * HH - 2 - i) : i;
}

template<int KK, bool EDGEL, bool EDGER>
__device__ __forceinline__ void run_band(
    const float* __restrict__ sp, float* __restrict__ dp,
    int g, int r0, int lane,
    float wu, float wl, float wc, float wr, float wd)
{
    // Interior strips keep lanes 2..29 (8-col halo/side covers KK<=8 stages of
    // 1-col/side garbage). Edge strips extend to the mirrored domain boundary.
    const int lo = EDGEL ? 0 : 2;
    const int hi = EDGER ? 31 : 29;
    const bool do_store = (lane >= lo && lane <= hi);
    const bool fixL = EDGEL && (lane == 0);
    const bool fixR = EDGER && (lane == 31);

    // Rolling window per stage s: a[s] = u_s[row-2], b[s] = u_s[row-1]
    float4 a[KK], b[KK];
#pragma unroll
    for (int s = 0; s < KK; ++s) {
        a[s] = make_float4(0.f, 0.f, 0.f, 0.f);
        b[s] = make_float4(0.f, 0.f, 0.f, 0.f);
    }

    const int niter = RB + 2 * KK;

    // Prefetch pipeline, depth 2 (reflect keeps all rows in-bounds).
    float4 p0 = ((const float4*)(sp + (size_t)reflect_row(r0 - KK)     * WW))[g];
    float4 p1 = ((const float4*)(sp + (size_t)reflect_row(r0 - KK + 1) * WW))[g];

#pragma unroll 2
    for (int m = 0; m < niter; ++m) {
        const int i = r0 - KK + m;   // input row index for stage 0

        // Shuffle batch: operands are iteration-start state only.
        float lv[KK], rv[KK];
#pragma unroll
        for (int s = 0; s < KK; ++s) {
            const float lu = __shfl_up_sync(0xffffffffu, b[s].w, 1);
            const float rd = __shfl_down_sync(0xffffffffu, b[s].x, 1);
            lv[s] = fixL ? b[s].y : lu;   // mirror col -1 -> col 1
            rv[s] = fixR ? b[s].z : rd;   // mirror col 1024 -> col 1022
        }

        float4 cur[KK + 1];
        cur[0] = p0;
        p0 = p1;
        p1 = ((const float4*)(sp + (size_t)reflect_row(i + 2) * WW))[g];

#pragma unroll
        for (int s = 1; s <= KK; ++s) {
            const float4 B = b[s - 1];    // center (iter-start state)
            const float4 A = a[s - 1];    // up     (iter-start state)
            const float4 D = cur[s - 1];  // down   (fresh — consume last)

            float4 bs;
            bs.x = fmaf(wu, A.x, fmaf(wl, lv[s - 1], fmaf(wr, B.y, wc * B.x)));
            bs.y = fmaf(wu, A.y, fmaf(wl, B.x,       fmaf(wr, B.z, wc * B.y)));
            bs.z = fmaf(wu, A.z, fmaf(wl, B.y,       fmaf(wr, B.w, wc * B.z)));
            bs.w = fmaf(wu, A.w, fmaf(wl, B.z,       fmaf(wr, rv[s - 1], wc * B.w)));

            float4 o;
            o.x = fmaf(wd, D.x, bs.x);
            o.y = fmaf(wd, D.y, bs.y);
            o.z = fmaf(wd, D.z, bs.z);
            o.w = fmaf(wd, D.w, bs.w);
            cur[s] = o;
        }

        // Final-stage row j = i - KK is a band row exactly when m >= 2*KK.
        if (m >= 2 * KK && do_store) {
            ((float4*)(dp + (size_t)(i - KK) * WW))[g] = cur[KK];
        }

#pragma unroll
        for (int s = 0; s < KK; ++s) {
            a[s] = b[s];
            b[s] = cur[s];
        }
    }
}

template<int KK>
__global__ __launch_bounds__(256, 2)
void fused_stencil(const float* __restrict__ src,
                   float* __restrict__ dst,
                   const float* __restrict__ wgt)
{
    const int strip = blockIdx.x;          // 0..8
    const int img   = blockIdx.y;          // 0..31
    const int warp  = threadIdx.x >> 5;    // band 0..7
    const int lane  = threadIdx.x & 31;

    const float* wp = wgt + (img & 1) * 9;   // OIHW (2,1,3,3), depthwise
    const float wu = wp[1];
    const float wl = wp[3];
    const float wc = wp[4];
    const float wr = wp[5];
    const float wd = wp[7];

    const float* sp = src + (size_t)img * PLANE_ELEMS;
    float*       dp = dst + (size_t)img * PLANE_ELEMS;

    const int g  = ((strip * 112) >> 2) + lane;   // lane's float4 column index
    const int r0 = warp * RB;

    if (strip == 0) {
        run_band<KK, true, false>(sp, dp, g, r0, lane, wu, wl, wc, wr, wd);
    } else if (strip == NSTRIP - 1) {
        run_band<KK, false, true>(sp, dp, g, r0, lane, wu, wl, wc, wr, wd);
    } else {
        run_band<KK, false, false>(sp, dp, g, r0, lane, wu, wl, wc, wr, wd);
    }
}

extern "C" void kernel_launch(void* const* d_in, const int* in_sizes, int n_in,
                              void* d_out, int out_size)
{
    const float* x   = (const float*)d_in[0];
    const float* wgt = (const float*)d_in[1];
    float* out = (float*)d_out;

    float* scratch = nullptr;
    cudaGetSymbolAddress((void**)&scratch, g_scratch);

    dim3 grid(NSTRIP, NPLANES);   // 9 strips x 32 planes = 288 blocks
    dim3 block(256);              // 8 warps = 8 row bands

    // 7 + 7 + 6 = 20 steps; d_out serves as intermediate (fully overwritten).
    fused_stencil<7><<<grid, block>>>(x,       out,     wgt);
    fused_stencil<7><<<grid, block>>>(out,     scratch, wgt);
    fused_stencil<6><<<grid, block>>>(scratch, out,     wgt);
}